// round 14
// baseline (speedup 1.0000x reference)
#include <cuda_runtime.h>
#include <cuda_fp16.h>
#include <math.h>
#include <stdint.h>

#define B_ 64
#define S_ 2048
#define D_ 512
#define A_ 256
#define BS_ (B_ * S_)

// Scratch (allocation-free rule: __device__ globals)
__device__ int    g_idx[BS_];             // per-batch compacted active s indices
__device__ int    g_cnt[B_];              // active count per batch
__device__ int    g_done[B_];             // finished-CTA ticket per batch
__device__ float  g_esum[B_];             // per-batch sum of exp(logit)
__device__ float  g_outacc[B_ * D_];      // unnormalized weighted sum
__device__ __half g_WT[A_ * D_];          // W^T fp16 (col-major B for mma)

// ---------------------------------------------------------------------------
// helpers
// ---------------------------------------------------------------------------
__device__ __forceinline__ uint32_t smem_u32(const void* p) {
    uint32_t a;
    asm("{ .reg .u64 t; cvta.to.shared.u64 t, %1; cvt.u32.u64 %0, t; }"
        : "=r"(a) : "l"(p));
    return a;
}

__device__ __forceinline__ void ldsm_x4(uint32_t addr, uint32_t& r0, uint32_t& r1,
                                        uint32_t& r2, uint32_t& r3) {
    asm volatile("ldmatrix.sync.aligned.m8n8.x4.shared.b16 {%0,%1,%2,%3}, [%4];"
                 : "=r"(r0), "=r"(r1), "=r"(r2), "=r"(r3) : "r"(addr));
}

__device__ __forceinline__ void mma_f16(float* d, const uint32_t* a,
                                        uint32_t b0, uint32_t b1) {
    asm volatile(
        "mma.sync.aligned.m16n8k16.row.col.f32.f16.f16.f32 "
        "{%0,%1,%2,%3}, {%4,%5,%6,%7}, {%8,%9}, {%0,%1,%2,%3};"
        : "+f"(d[0]), "+f"(d[1]), "+f"(d[2]), "+f"(d[3])
        : "r"(a[0]), "r"(a[1]), "r"(a[2]), "r"(a[3]), "r"(b0), "r"(b1));
}

__device__ __forceinline__ void cp16(uint32_t saddr, const void* gptr) {
    asm volatile("cp.async.cg.shared.global [%0], [%1], 16;"
                 :: "r"(saddr), "l"(gptr));
}
__device__ __forceinline__ void cp_commit() {
    asm volatile("cp.async.commit_group;" ::: "memory");
}
__device__ __forceinline__ void cp_wait0() {
    asm volatile("cp.async.wait_group 0;" ::: "memory");
}

__device__ __forceinline__ uint32_t pack_h2(float a, float b) {
    __half2 h = __floats2half2_rn(a, b);
    return *(uint32_t*)&h;
}

// tanh via ex2/rcp MUFU path: err ~1e-6
__device__ __forceinline__ float tanh_fast(float x) {
    float e = __expf(2.f * x);
    return 1.f - __fdividef(2.f, e + 1.f);
}

// ---------------------------------------------------------------------------
// Kernel 0: per-batch mask compaction + coalesced W transpose + zero accum.
// ---------------------------------------------------------------------------
#define TW_STRIDE 20

__global__ __launch_bounds__(1024) void compact_kernel(
    const int* __restrict__ mask, const float* __restrict__ W)
{
    const int b = blockIdx.x;
    const int tid = threadIdx.x;
    const int lane = tid & 31, w = tid >> 5;
    __shared__ int wbase[32];
    __shared__ __half t_w[256 * TW_STRIDE];

    if (tid < 512) g_outacc[b * 512 + tid] = 0.f;
    if (tid == 0) { g_esum[b] = 0.f; g_done[b] = 0; }

    if (b < 32) {
        const int d0 = b * 16;
#pragma unroll
        for (int p = 0; p < 4; p++) {
            int e = p * 1024 + tid;
            int d = e >> 8, a = e & 255;
            t_w[a * TW_STRIDE + d] = __float2half_rn(W[(d0 + d) * A_ + a]);
        }
        __syncthreads();
        {
            int a = tid >> 2, dq = (tid & 3) << 2;
            *(uint2*)(&g_WT[a * D_ + d0 + dq]) = *(uint2*)(&t_w[a * TW_STRIDE + dq]);
        }
    }

    int m0 = mask[b * S_ + tid * 2];
    int m1 = mask[b * S_ + tid * 2 + 1];
    int c = (m0 != 0) + (m1 != 0);

    int inc = c;
#pragma unroll
    for (int off = 1; off < 32; off <<= 1) {
        int n = __shfl_up_sync(0xffffffffu, inc, off);
        if (lane >= off) inc += n;
    }
    if (lane == 31) wbase[w] = inc;
    __syncthreads();
    if (tid == 0) {
        int r = 0;
#pragma unroll
        for (int i = 0; i < 32; i++) { int t = wbase[i]; wbase[i] = r; r += t; }
        g_cnt[b] = r;
    }
    __syncthreads();
    int base = wbase[w] + inc - c;
    if (m0 != 0) g_idx[b * S_ + base++] = tid * 2;
    if (m1 != 0) g_idx[b * S_ + base]   = tid * 2 + 1;
}

// ---------------------------------------------------------------------------
// Kernel A: 1024 threads (32 warps), 128x256 tile, warp tile 32x32, TKC=64
// (8 chunks -> 8 barriers). fp16 mma GEMM on compacted rows + SMEM-fused
// wsum + last-CTA scaling. Full 128x512 fp16 x tile SMEM-resident.
// ---------------------------------------------------------------------------
#define TKC 64
#define NCHUNK (D_ / TKC)           // 8
#define WROW 144                    // W tile row stride (128B data + 16 pad)
#define FROW 1040                   // full x tile row stride (512*2 + 16)
#define OFF_W  0                            // [2 stages]
#define WSTAGE (256 * WROW)                 // 36864 per stage
#define OFF_FULL (2 * WSTAGE)               // 73728, 128*1040 = 133120
#define OFF_RED (OFF_FULL + 128 * FROW)     // 206848 float[128]
#define OFF_E   (OFF_RED + 512)             // float[128]
#define OFF_IDX (OFF_E + 512)               // int[128]
#define OFF_PART (OFF_IDX + 512)            // float[4]
#define OFF_FLAG (OFF_PART + 16)            // int[1]
#define SMEM_BYTES (OFF_FLAG + 16)          // 208416
// sm_wsum[16][512] floats (32KB) reuses bytes [0, 73728) after mainloop

__global__ __launch_bounds__(1024, 1) void logits_mma_kernel(
    const float* __restrict__ x, const float* __restrict__ bias,
    const float* __restrict__ u, float* __restrict__ out)
{
    extern __shared__ char smem[];
    const uint32_t sb = smem_u32(smem);
    float* sm_red  = (float*)(smem + OFF_RED);
    float* sm_e    = (float*)(smem + OFF_E);
    int*   sm_idx  = (int*)(smem + OFF_IDX);
    float* sm_part = (float*)(smem + OFF_PART);
    int*   sm_flag = (int*)(smem + OFF_FLAG);
    float* sm_wsum = (float*)(smem);

    const int b    = blockIdx.x;
    const int jb   = blockIdx.y * 128;
    const int cnt  = g_cnt[b];
    if (jb >= cnt) return;
    const int nact = (cnt + 127) >> 7;

    const int tid  = threadIdx.x;
    const int wid  = tid >> 5;
    const int lane = tid & 31;
    const int warp_m = wid & 3;          // 32-row group
    const int warp_n = wid >> 2;         // 32-col group (0..7)

    if (tid < 128) {
        sm_red[tid] = 0.f;
        int j = jb + tid;
        sm_idx[tid] = g_idx[b * S_ + (j < cnt ? j : cnt - 1)];
    }
    __syncthreads();

    // x load mapping: 8 threads per row, 8 floats (2 x float4) each
    const int row_x = tid >> 3;
    const int kq_x  = (tid & 7) * 8;
    const float* gx = x + ((size_t)b * S_ + sm_idx[row_x]) * D_ + kq_x;
    char* full_out = smem + OFF_FULL + row_x * FROW + kq_x * 2;

    // W cp.async mapping: 4 threads per row (n), 2x16B each
    const int n_w  = tid >> 2;
    const int q_w  = tid & 3;
    const __half* gw = g_WT + n_w * D_ + q_w * 16;
    const uint32_t wdst_row = n_w * WROW + q_w * 32;

    float acc[2][4][4];
#pragma unroll
    for (int i = 0; i < 2; i++)
#pragma unroll
        for (int j = 0; j < 4; j++)
#pragma unroll
            for (int k = 0; k < 4; k++) acc[i][j][k] = 0.f;

    // ---- preload chunk 0 ----
    {
        float4 v0 = *(const float4*)(gx);
        float4 v1 = *(const float4*)(gx + 4);
        uint4 hi;
        hi.x = pack_h2(v0.x, v0.y); hi.y = pack_h2(v0.z, v0.w);
        hi.z = pack_h2(v1.x, v1.y); hi.w = pack_h2(v1.z, v1.w);
        *(uint4*)(full_out) = hi;

        cp16(sb + OFF_W + wdst_row,      gw);
        cp16(sb + OFF_W + wdst_row + 16, gw + 8);
        cp_commit();
    }

    // ldmatrix lane addressing
    const int a_row  = (lane & 15);
    const int a_kb   = (lane >> 4) * 16;
    const int t      = lane >> 3;
    const int b_noff = (lane & 7) + 8 * (t >> 1);
    const int b_kb   = 16 * (t & 1);
    const uint32_t xfull = sb + OFF_FULL;

    for (int c = 0; c < NCHUNK; c++) {
        const int st  = c & 1;
        const int stn = (c + 1) & 1;

        cp_wait0();
        __syncthreads();   // chunk-c x writes + W stage visible

        // prefetch chunk c+1 (latency hidden under this chunk's mma)
        if (c + 1 < NCHUNK) {
            const __half* sh = gw + (c + 1) * TKC;
            cp16(sb + OFF_W + stn * WSTAGE + wdst_row,      sh);
            cp16(sb + OFF_W + stn * WSTAGE + wdst_row + 16, sh + 8);
            cp_commit();
            float4 v0 = *(const float4*)(gx + (c + 1) * TKC);
            float4 v1 = *(const float4*)(gx + (c + 1) * TKC + 4);
            uint4 hi;
            hi.x = pack_h2(v0.x, v0.y); hi.y = pack_h2(v0.z, v0.w);
            hi.z = pack_h2(v1.x, v1.y); hi.w = pack_h2(v1.z, v1.w);
            *(uint4*)(full_out + (c + 1) * (TKC * 2)) = hi;
        }

        const uint32_t wh = sb + OFF_W + st * WSTAGE;

#pragma unroll
        for (int ks = 0; ks < 4; ks++) {
            uint32_t ah[2][4];
#pragma unroll
            for (int mt = 0; mt < 2; mt++) {
                uint32_t ra = (warp_m * 32 + mt * 16 + a_row) * FROW
                            + c * 128 + ks * 32 + a_kb;
                ldsm_x4(xfull + ra, ah[mt][0], ah[mt][1], ah[mt][2], ah[mt][3]);
            }
#pragma unroll
            for (int pair = 0; pair < 2; pair++) {
                uint32_t rb = (warp_n * 32 + pair * 16 + b_noff) * WROW
                            + ks * 32 + b_kb;
                uint32_t bh0, bh1, bh2, bh3;
                ldsm_x4(wh + rb, bh0, bh1, bh2, bh3);
#pragma unroll
                for (int mt = 0; mt < 2; mt++) {
                    mma_f16(acc[mt][pair * 2 + 0], ah[mt], bh0, bh1);
                    mma_f16(acc[mt][pair * 2 + 1], ah[mt], bh2, bh3);
                }
            }
        }
    }

    // ---- epilogue 1: tanh(acc + bias) * u, reduce over cols ----
#pragma unroll
    for (int mt = 0; mt < 2; mt++) {
        float r0acc = 0.f, r1acc = 0.f;
#pragma unroll
        for (int j = 0; j < 4; j++) {
            int col = warp_n * 32 + j * 8 + 2 * (lane & 3);
            float b0 = bias[col], b1 = bias[col + 1];
            float u0 = u[col],    u1 = u[col + 1];
            r0acc += tanh_fast(acc[mt][j][0] + b0) * u0
                   + tanh_fast(acc[mt][j][1] + b1) * u1;
            r1acc += tanh_fast(acc[mt][j][2] + b0) * u0
                   + tanh_fast(acc[mt][j][3] + b1) * u1;
        }
        r0acc += __shfl_xor_sync(0xffffffffu, r0acc, 1);
        r0acc += __shfl_xor_sync(0xffffffffu, r0acc, 2);
        r1acc += __shfl_xor_sync(0xffffffffu, r1acc, 1);
        r1acc += __shfl_xor_sync(0xffffffffu, r1acc, 2);
        if ((lane & 3) == 0) {
            int lrow = warp_m * 32 + mt * 16 + (lane >> 2);
            atomicAdd(&sm_red[lrow],     r0acc);
            atomicAdd(&sm_red[lrow + 8], r1acc);
        }
    }
    __syncthreads();

    // ---- epilogue 2: e = exp(logit) (0 past cnt), esum partial ----
    if (tid < 128) {
        int j = jb + tid;
        float e = (j < cnt) ? expf(sm_red[tid]) : 0.f;
        sm_e[tid] = e;
        float v = e;
#pragma unroll
        for (int off = 16; off > 0; off >>= 1)
            v += __shfl_xor_sync(0xffffffffu, v, off);
        if (lane == 0) sm_part[wid] = v;
    }
    __syncthreads();
    if (tid == 0)
        atomicAdd(&g_esum[b], sm_part[0] + sm_part[1] + sm_part[2] + sm_part[3]);

    // ---- epilogue 3: fused weighted sum from SMEM-resident x tile ----
    {
        const int g  = tid >> 6;               // 0..15
        const int d8 = (tid & 63) * 8;
        float a8[8];
#pragma unroll
        for (int i = 0; i < 8; i++) a8[i] = 0.f;

        const char* xb = smem + OFF_FULL + d8 * 2;
#pragma unroll 4
        for (int j = g; j < 128; j += 16) {
            uint4 v = *(const uint4*)(xb + j * FROW);
            float w = sm_e[j];
            float2 f0 = __half22float2(*(__half2*)&v.x);
            float2 f1 = __half22float2(*(__half2*)&v.y);
            float2 f2 = __half22float2(*(__half2*)&v.z);
            float2 f3 = __half22float2(*(__half2*)&v.w);
            a8[0] = fmaf(f0.x, w, a8[0]); a8[1] = fmaf(f0.y, w, a8[1]);
            a8[2] = fmaf(f1.x, w, a8[2]); a8[3] = fmaf(f1.y, w, a8[3]);
            a8[4] = fmaf(f2.x, w, a8[4]); a8[5] = fmaf(f2.y, w, a8[5]);
            a8[6] = fmaf(f3.x, w, a8[6]); a8[7] = fmaf(f3.y, w, a8[7]);
        }
        __syncthreads();   // W-stage smem now reusable as sm_wsum
        *(float4*)(&sm_wsum[g * 512 + d8])     = make_float4(a8[0], a8[1], a8[2], a8[3]);
        *(float4*)(&sm_wsum[g * 512 + d8 + 4]) = make_float4(a8[4], a8[5], a8[6], a8[7]);
    }
    __syncthreads();
    if (tid < 512) {
        float s = 0.f;
#pragma unroll
        for (int g = 0; g < 16; g++) s += sm_wsum[g * 512 + tid];
        atomicAdd(&g_outacc[b * 512 + tid], s);
    }
    __syncthreads();

    // ---- epilogue 4: last CTA for this batch writes the scaled output ----
    if (tid == 0) {
        __threadfence();
        int ticket = atomicAdd(&g_done[b], 1);
        sm_flag[0] = (ticket == nact - 1);
    }
    __syncthreads();
    if (sm_flag[0] && tid < 512) {
        __threadfence();
        const float inv = __fdividef(1.f, g_esum[b] + 1e-7f);
        out[b * 512 + tid] = g_outacc[b * 512 + tid] * inv;
    }
}

// ---------------------------------------------------------------------------
extern "C" void kernel_launch(void* const* d_in, const int* in_sizes, int n_in,
                              void* d_out, int out_size)
{
    const float* x    = (const float*)d_in[0];
    const int*   mask = (const int*)d_in[1];
    const float* W    = (const float*)d_in[2];
    const float* bias = (const float*)d_in[3];
    const float* u    = (const float*)d_in[4];
    float*       out  = (float*)d_out;

    cudaFuncSetAttribute(logits_mma_kernel,
                         cudaFuncAttributeMaxDynamicSharedMemorySize, SMEM_BYTES);

    compact_kernel<<<B_, 1024>>>(mask, W);
    logits_mma_kernel<<<dim3(B_, 16), 1024, SMEM_BYTES>>>(x, bias, u, out);
}

// round 15
// speedup vs baseline: 1.1611x; 1.1611x over previous
#include <cuda_runtime.h>
#include <cuda_fp16.h>
#include <math.h>
#include <stdint.h>

#define B_ 64
#define S_ 2048
#define D_ 512
#define A_ 256
#define BS_ (B_ * S_)

// Scratch (allocation-free rule: __device__ globals)
__device__ int    g_idx[BS_];             // per-batch compacted active s indices
__device__ int    g_cnt[B_];              // active count per batch
__device__ int    g_done[B_];             // finished-CTA ticket per batch
__device__ float  g_esum[B_];             // per-batch sum of exp(logit)
__device__ float  g_outacc[B_ * D_];      // unnormalized weighted sum
__device__ __half g_WT[A_ * D_];          // W^T fp16 (col-major B for mma)

// ---------------------------------------------------------------------------
// helpers
// ---------------------------------------------------------------------------
__device__ __forceinline__ uint32_t smem_u32(const void* p) {
    uint32_t a;
    asm("{ .reg .u64 t; cvta.to.shared.u64 t, %1; cvt.u32.u64 %0, t; }"
        : "=r"(a) : "l"(p));
    return a;
}

__device__ __forceinline__ void ldsm_x4(uint32_t addr, uint32_t& r0, uint32_t& r1,
                                        uint32_t& r2, uint32_t& r3) {
    asm volatile("ldmatrix.sync.aligned.m8n8.x4.shared.b16 {%0,%1,%2,%3}, [%4];"
                 : "=r"(r0), "=r"(r1), "=r"(r2), "=r"(r3) : "r"(addr));
}

__device__ __forceinline__ void mma_f16(float* d, const uint32_t* a,
                                        uint32_t b0, uint32_t b1) {
    asm volatile(
        "mma.sync.aligned.m16n8k16.row.col.f32.f16.f16.f32 "
        "{%0,%1,%2,%3}, {%4,%5,%6,%7}, {%8,%9}, {%0,%1,%2,%3};"
        : "+f"(d[0]), "+f"(d[1]), "+f"(d[2]), "+f"(d[3])
        : "r"(a[0]), "r"(a[1]), "r"(a[2]), "r"(a[3]), "r"(b0), "r"(b1));
}

__device__ __forceinline__ void cp16(uint32_t saddr, const void* gptr) {
    asm volatile("cp.async.cg.shared.global [%0], [%1], 16;"
                 :: "r"(saddr), "l"(gptr));
}
__device__ __forceinline__ void cp_commit() {
    asm volatile("cp.async.commit_group;" ::: "memory");
}
__device__ __forceinline__ void cp_wait0() {
    asm volatile("cp.async.wait_group 0;" ::: "memory");
}

__device__ __forceinline__ uint32_t pack_h2(float a, float b) {
    __half2 h = __floats2half2_rn(a, b);
    return *(uint32_t*)&h;
}

// tanh via ex2/rcp MUFU path: err ~1e-6
__device__ __forceinline__ float tanh_fast(float x) {
    float e = __expf(2.f * x);
    return 1.f - __fdividef(2.f, e + 1.f);
}

// ---------------------------------------------------------------------------
// Kernel 0: per-batch mask compaction + coalesced W transpose + zero accum.
// ---------------------------------------------------------------------------
#define TW_STRIDE 20

__global__ __launch_bounds__(1024) void compact_kernel(
    const int* __restrict__ mask, const float* __restrict__ W)
{
    const int b = blockIdx.x;
    const int tid = threadIdx.x;
    const int lane = tid & 31, w = tid >> 5;
    __shared__ int wbase[32];
    __shared__ __half t_w[256 * TW_STRIDE];

    if (tid < 512) g_outacc[b * 512 + tid] = 0.f;
    if (tid == 0) { g_esum[b] = 0.f; g_done[b] = 0; }

    if (b < 32) {
        const int d0 = b * 16;
#pragma unroll
        for (int p = 0; p < 4; p++) {
            int e = p * 1024 + tid;
            int d = e >> 8, a = e & 255;
            t_w[a * TW_STRIDE + d] = __float2half_rn(W[(d0 + d) * A_ + a]);
        }
        __syncthreads();
        {
            int a = tid >> 2, dq = (tid & 3) << 2;
            *(uint2*)(&g_WT[a * D_ + d0 + dq]) = *(uint2*)(&t_w[a * TW_STRIDE + dq]);
        }
    }

    int m0 = mask[b * S_ + tid * 2];
    int m1 = mask[b * S_ + tid * 2 + 1];
    int c = (m0 != 0) + (m1 != 0);

    int inc = c;
#pragma unroll
    for (int off = 1; off < 32; off <<= 1) {
        int n = __shfl_up_sync(0xffffffffu, inc, off);
        if (lane >= off) inc += n;
    }
    if (lane == 31) wbase[w] = inc;
    __syncthreads();
    if (tid == 0) {
        int r = 0;
#pragma unroll
        for (int i = 0; i < 32; i++) { int t = wbase[i]; wbase[i] = r; r += t; }
        g_cnt[b] = r;
    }
    __syncthreads();
    int base = wbase[w] + inc - c;
    if (m0 != 0) g_idx[b * S_ + base++] = tid * 2;
    if (m1 != 0) g_idx[b * S_ + base]   = tid * 2 + 1;
}

// ---------------------------------------------------------------------------
// Kernel A: 1024 threads (32 warps), 128x256 tile, warp tile 32x32, TKC=32.
// fp16 mma GEMM on compacted rows + SMEM-fused wsum + last-CTA scaling.
// Full 128x512 fp16 x tile SMEM-resident; A ldsm'd directly from it.
// x prefetch is SPLIT: global load issued before the mma block, convert+
// store to the disjoint c+1 region after it (hides LDG latency under mma).
// ---------------------------------------------------------------------------
#define TKC 32
#define NCHUNK (D_ / TKC)           // 16
#define XROW 80                     // W tile row pad (80B)
#define FROW 1040                   // full x tile row stride (512*2 + 16)
#define OFF_W  0                            // [2 stages]
#define WSTAGE (256 * XROW)                 // 20480 per stage
#define OFF_FULL (2 * WSTAGE)               // 40960, 128*1040 = 133120
#define OFF_RED (OFF_FULL + 128 * FROW)     // 174080 float[128]
#define OFF_E   (OFF_RED + 512)             // float[128]
#define OFF_IDX (OFF_E + 512)               // int[128]
#define OFF_PART (OFF_IDX + 512)            // float[4]
#define OFF_FLAG (OFF_PART + 16)            // int[1]
#define SMEM_BYTES (OFF_FLAG + 16)          // 175136
// sm_wsum[16][512] floats (32KB) reuses bytes [0, 40960) after mainloop

__global__ __launch_bounds__(1024, 1) void logits_mma_kernel(
    const float* __restrict__ x, const float* __restrict__ bias,
    const float* __restrict__ u, float* __restrict__ out)
{
    extern __shared__ char smem[];
    const uint32_t sb = smem_u32(smem);
    float* sm_red  = (float*)(smem + OFF_RED);
    float* sm_e    = (float*)(smem + OFF_E);
    int*   sm_idx  = (int*)(smem + OFF_IDX);
    float* sm_part = (float*)(smem + OFF_PART);
    int*   sm_flag = (int*)(smem + OFF_FLAG);
    float* sm_wsum = (float*)(smem);

    const int b    = blockIdx.x;
    const int jb   = blockIdx.y * 128;
    const int cnt  = g_cnt[b];
    if (jb >= cnt) return;
    const int nact = (cnt + 127) >> 7;

    const int tid  = threadIdx.x;
    const int wid  = tid >> 5;
    const int lane = tid & 31;
    const int warp_m = wid & 3;          // 32-row group
    const int warp_n = wid >> 2;         // 32-col group (0..7)

    if (tid < 128) {
        sm_red[tid] = 0.f;
        int j = jb + tid;
        sm_idx[tid] = g_idx[b * S_ + (j < cnt ? j : cnt - 1)];
    }
    __syncthreads();

    // x load mapping: 8 threads per row, float4 (4 floats) each
    const int row_x = tid >> 3;
    const int kq_x  = (tid & 7) * 4;
    const float* gx = x + ((size_t)b * S_ + sm_idx[row_x]) * D_ + kq_x;
    char* full_out = smem + OFF_FULL + row_x * FROW + kq_x * 2;

    // W cp.async mapping: 4 threads per row (n), 16B each
    const int n_w  = tid >> 2;
    const int q_w  = tid & 3;
    const __half* gw = g_WT + n_w * D_ + q_w * 8;
    const uint32_t wdst_row = n_w * XROW + q_w * 16;

    float acc[2][4][4];
#pragma unroll
    for (int i = 0; i < 2; i++)
#pragma unroll
        for (int j = 0; j < 4; j++)
#pragma unroll
            for (int k = 0; k < 4; k++) acc[i][j][k] = 0.f;

    // ---- preload chunk 0 ----
    {
        float4 v = *(const float4*)(gx);
        uint2 hi;
        hi.x = pack_h2(v.x, v.y); hi.y = pack_h2(v.z, v.w);
        *(uint2*)(full_out) = hi;

        cp16(sb + OFF_W + wdst_row, gw);
        cp_commit();
    }

    // ldmatrix lane addressing
    const int a_row  = (lane & 15);
    const int a_kb   = (lane >> 4) * 16;
    const int t      = lane >> 3;
    const int b_noff = (lane & 7) + 8 * (t >> 1);
    const int b_kb   = 16 * (t & 1);
    const uint32_t xfull = sb + OFF_FULL;

    for (int c = 0; c < NCHUNK; c++) {
        const int st  = c & 1;
        const int stn = (c + 1) & 1;

        cp_wait0();
        __syncthreads();   // chunk-c x writes + W stage visible

        // kick off chunk c+1: W cp.async + x GLOBAL LOAD ONLY (store deferred
        // past the mma block so the LDG latency hides under tensor work)
        float4 xv;
        if (c + 1 < NCHUNK) {
            cp16(sb + OFF_W + stn * WSTAGE + wdst_row, gw + (c + 1) * TKC);
            cp_commit();
            xv = *(const float4*)(gx + (c + 1) * TKC);
        }

        const uint32_t wh = sb + OFF_W + st * WSTAGE;

#pragma unroll
        for (int ks = 0; ks < 2; ks++) {
            uint32_t ah[2][4];
#pragma unroll
            for (int mt = 0; mt < 2; mt++) {
                uint32_t ra = (warp_m * 32 + mt * 16 + a_row) * FROW
                            + c * 64 + ks * 32 + a_kb;
                ldsm_x4(xfull + ra, ah[mt][0], ah[mt][1], ah[mt][2], ah[mt][3]);
            }
#pragma unroll
            for (int pair = 0; pair < 2; pair++) {
                uint32_t rb = (warp_n * 32 + pair * 16 + b_noff) * XROW + ks * 32 + b_kb;
                uint32_t bh0, bh1, bh2, bh3;
                ldsm_x4(wh + rb, bh0, bh1, bh2, bh3);
#pragma unroll
                for (int mt = 0; mt < 2; mt++) {
                    mma_f16(acc[mt][pair * 2 + 0], ah[mt], bh0, bh1);
                    mma_f16(acc[mt][pair * 2 + 1], ah[mt], bh2, bh3);
                }
            }
        }

        // deferred convert + store of chunk c+1 (disjoint region; ordered by
        // the next iteration's barrier before any reader touches it)
        if (c + 1 < NCHUNK) {
            uint2 hi;
            hi.x = pack_h2(xv.x, xv.y); hi.y = pack_h2(xv.z, xv.w);
            *(uint2*)(full_out + (c + 1) * (TKC * 2)) = hi;
        }
    }

    // ---- epilogue 1: tanh(acc + bias) * u, reduce over cols ----
#pragma unroll
    for (int mt = 0; mt < 2; mt++) {
        float r0acc = 0.f, r1acc = 0.f;
#pragma unroll
        for (int j = 0; j < 4; j++) {
            int col = warp_n * 32 + j * 8 + 2 * (lane & 3);
            float b0 = bias[col], b1 = bias[col + 1];
            float u0 = u[col],    u1 = u[col + 1];
            r0acc += tanh_fast(acc[mt][j][0] + b0) * u0
                   + tanh_fast(acc[mt][j][1] + b1) * u1;
            r1acc += tanh_fast(acc[mt][j][2] + b0) * u0
                   + tanh_fast(acc[mt][j][3] + b1) * u1;
        }
        r0acc += __shfl_xor_sync(0xffffffffu, r0acc, 1);
        r0acc += __shfl_xor_sync(0xffffffffu, r0acc, 2);
        r1acc += __shfl_xor_sync(0xffffffffu, r1acc, 1);
        r1acc += __shfl_xor_sync(0xffffffffu, r1acc, 2);
        if ((lane & 3) == 0) {
            int lrow = warp_m * 32 + mt * 16 + (lane >> 2);
            atomicAdd(&sm_red[lrow],     r0acc);
            atomicAdd(&sm_red[lrow + 8], r1acc);
        }
    }
    __syncthreads();

    // ---- epilogue 2: e = exp(logit) (0 past cnt), esum partial ----
    if (tid < 128) {
        int j = jb + tid;
        float e = (j < cnt) ? expf(sm_red[tid]) : 0.f;
        sm_e[tid] = e;
        float v = e;
#pragma unroll
        for (int off = 16; off > 0; off >>= 1)
            v += __shfl_xor_sync(0xffffffffu, v, off);
        if (lane == 0) sm_part[wid] = v;
    }
    __syncthreads();
    if (tid == 0)
        atomicAdd(&g_esum[b], sm_part[0] + sm_part[1] + sm_part[2] + sm_part[3]);

    // ---- epilogue 3: fused weighted sum from SMEM-resident x tile ----
    {
        const int g  = tid >> 6;               // 0..15
        const int d8 = (tid & 63) * 8;
        float a8[8];
#pragma unroll
        for (int i = 0; i < 8; i++) a8[i] = 0.f;

        const char* xb = smem + OFF_FULL + d8 * 2;
#pragma unroll 4
        for (int j = g; j < 128; j += 16) {
            uint4 v = *(const uint4*)(xb + j * FROW);
            float w = sm_e[j];
            float2 f0 = __half22float2(*(__half2*)&v.x);
            float2 f1 = __half22float2(*(__half2*)&v.y);
            float2 f2 = __half22float2(*(__half2*)&v.z);
            float2 f3 = __half22float2(*(__half2*)&v.w);
            a8[0] = fmaf(f0.x, w, a8[0]); a8[1] = fmaf(f0.y, w, a8[1]);
            a8[2] = fmaf(f1.x, w, a8[2]); a8[3] = fmaf(f1.y, w, a8[3]);
            a8[4] = fmaf(f2.x, w, a8[4]); a8[5] = fmaf(f2.y, w, a8[5]);
            a8[6] = fmaf(f3.x, w, a8[6]); a8[7] = fmaf(f3.y, w, a8[7]);
        }
        __syncthreads();   // W-stage smem now reusable as sm_wsum
        *(float4*)(&sm_wsum[g * 512 + d8])     = make_float4(a8[0], a8[1], a8[2], a8[3]);
        *(float4*)(&sm_wsum[g * 512 + d8 + 4]) = make_float4(a8[4], a8[5], a8[6], a8[7]);
    }
    __syncthreads();
    if (tid < 512) {
        float s = 0.f;
#pragma unroll
        for (int g = 0; g < 16; g++) s += sm_wsum[g * 512 + tid];
        atomicAdd(&g_outacc[b * 512 + tid], s);
    }
    __syncthreads();

    // ---- epilogue 4: last CTA for this batch writes the scaled output ----
    if (tid == 0) {
        __threadfence();
        int ticket = atomicAdd(&g_done[b], 1);
        sm_flag[0] = (ticket == nact - 1);
    }
    __syncthreads();
    if (sm_flag[0] && tid < 512) {
        __threadfence();
        const float inv = __fdividef(1.f, g_esum[b] + 1e-7f);
        out[b * 512 + tid] = g_outacc[b * 512 + tid] * inv;
    }
}

// ---------------------------------------------------------------------------
extern "C" void kernel_launch(void* const* d_in, const int* in_sizes, int n_in,
                              void* d_out, int out_size)
{
    const float* x    = (const float*)d_in[0];
    const int*   mask = (const int*)d_in[1];
    const float* W    = (const float*)d_in[2];
    const float* bias = (const float*)d_in[3];
    const float* u    = (const float*)d_in[4];
    float*       out  = (float*)d_out;

    cudaFuncSetAttribute(logits_mma_kernel,
                         cudaFuncAttributeMaxDynamicSharedMemorySize, SMEM_BYTES);

    compact_kernel<<<B_, 1024>>>(mask, W);
    logits_mma_kernel<<<dim3(B_, 16), 1024, SMEM_BYTES>>>(x, bias, u, out);
}

// round 16
// speedup vs baseline: 1.1799x; 1.0162x over previous
#include <cuda_runtime.h>
#include <cuda_fp16.h>
#include <math.h>
#include <stdint.h>

#define B_ 64
#define S_ 2048
#define D_ 512
#define A_ 256
#define BS_ (B_ * S_)

// Scratch (allocation-free rule: __device__ globals)
__device__ int    g_idx[BS_];             // per-batch compacted active s indices
__device__ int    g_cnt[B_];              // active count per batch
__device__ int    g_done[B_];             // finished-CTA ticket per batch
__device__ float  g_esum[B_];             // per-batch sum of exp(logit)
__device__ float  g_outacc[B_ * D_];      // unnormalized weighted sum
__device__ __half g_WT[A_ * D_];          // W^T fp16 (col-major B for mma)

// ---------------------------------------------------------------------------
// helpers
// ---------------------------------------------------------------------------
__device__ __forceinline__ uint32_t smem_u32(const void* p) {
    uint32_t a;
    asm("{ .reg .u64 t; cvta.to.shared.u64 t, %1; cvt.u32.u64 %0, t; }"
        : "=r"(a) : "l"(p));
    return a;
}

__device__ __forceinline__ void ldsm_x4(uint32_t addr, uint32_t& r0, uint32_t& r1,
                                        uint32_t& r2, uint32_t& r3) {
    asm volatile("ldmatrix.sync.aligned.m8n8.x4.shared.b16 {%0,%1,%2,%3}, [%4];"
                 : "=r"(r0), "=r"(r1), "=r"(r2), "=r"(r3) : "r"(addr));
}

__device__ __forceinline__ void mma_f16(float* d, const uint32_t* a,
                                        uint32_t b0, uint32_t b1) {
    asm volatile(
        "mma.sync.aligned.m16n8k16.row.col.f32.f16.f16.f32 "
        "{%0,%1,%2,%3}, {%4,%5,%6,%7}, {%8,%9}, {%0,%1,%2,%3};"
        : "+f"(d[0]), "+f"(d[1]), "+f"(d[2]), "+f"(d[3])
        : "r"(a[0]), "r"(a[1]), "r"(a[2]), "r"(a[3]), "r"(b0), "r"(b1));
}

__device__ __forceinline__ void cp16(uint32_t saddr, const void* gptr) {
    asm volatile("cp.async.cg.shared.global [%0], [%1], 16;"
                 :: "r"(saddr), "l"(gptr));
}
__device__ __forceinline__ void cp_commit() {
    asm volatile("cp.async.commit_group;" ::: "memory");
}
__device__ __forceinline__ void cp_wait0() {
    asm volatile("cp.async.wait_group 0;" ::: "memory");
}

__device__ __forceinline__ uint32_t pack_h2(float a, float b) {
    __half2 h = __floats2half2_rn(a, b);
    return *(uint32_t*)&h;
}

// tanh via ex2/rcp MUFU path: err ~1e-6
__device__ __forceinline__ float tanh_fast(float x) {
    float e = __expf(2.f * x);
    return 1.f - __fdividef(2.f, e + 1.f);
}

// ---------------------------------------------------------------------------
// Kernel 0: per-batch mask compaction + W transpose + zero accum.
// grid B_ (64), 1024 threads. EVERY block transposes an 8-wide d-band of W
// (2 independent LDG phases, 1 barrier, 1 store phase -> short latency chain,
// instruction-overlapped with the mask loads/scan).
// ---------------------------------------------------------------------------
#define TW_STRIDE 12    // halves per a-row in transpose tile (24B)

__global__ __launch_bounds__(1024) void compact_kernel(
    const int* __restrict__ mask, const float* __restrict__ W)
{
    const int b = blockIdx.x;
    const int tid = threadIdx.x;
    const int lane = tid & 31, w = tid >> 5;
    __shared__ int wbase[32];
    __shared__ __half t_w[256 * TW_STRIDE];   // 6144 B

    if (tid < 512) g_outacc[b * 512 + tid] = 0.f;
    if (tid == 0) { g_esum[b] = 0.f; g_done[b] = 0; }

    // mask loads issued EARLY (independent of W work; overlap latencies)
    int m0 = mask[b * S_ + tid * 2];
    int m1 = mask[b * S_ + tid * 2 + 1];

    // ---- W transpose band: every block, d in [8b, 8b+8) ----
    {
        const int d0 = b * 8;
        // fill: 2048 elems, 2 independent phases of 1024 coalesced loads
#pragma unroll
        for (int p = 0; p < 2; p++) {
            int e = p * 1024 + tid;        // 0..2047
            int d = e >> 8, a = e & 255;   // d 0..7, a 0..255
            t_w[a * TW_STRIDE + d] = __float2half_rn(W[(d0 + d) * A_ + a]);
        }
        __syncthreads();
        // drain: 1024 threads, 4B (2 halves) each -> 8 halves per a-row
        {
            int a = tid >> 2, dq = (tid & 3) * 2;
            *(uint32_t*)(&g_WT[a * D_ + d0 + dq]) =
                *(uint32_t*)(&t_w[a * TW_STRIDE + dq]);
        }
    }

    // ---- mask compaction scan ----
    int c = (m0 != 0) + (m1 != 0);

    int inc = c;
#pragma unroll
    for (int off = 1; off < 32; off <<= 1) {
        int n = __shfl_up_sync(0xffffffffu, inc, off);
        if (lane >= off) inc += n;
    }
    if (lane == 31) wbase[w] = inc;
    __syncthreads();
    if (tid == 0) {
        int r = 0;
#pragma unroll
        for (int i = 0; i < 32; i++) { int t = wbase[i]; wbase[i] = r; r += t; }
        g_cnt[b] = r;
    }
    __syncthreads();
    int base = wbase[w] + inc - c;
    if (m0 != 0) g_idx[b * S_ + base++] = tid * 2;
    if (m1 != 0) g_idx[b * S_ + base]   = tid * 2 + 1;
}

// ---------------------------------------------------------------------------
// Kernel A: 1024 threads (32 warps), 128x256 tile, warp tile 32x32, TKC=32.
// fp16 mma GEMM on compacted rows + SMEM-fused wsum + last-CTA scaling.
// Full 128x512 fp16 x tile SMEM-resident; A ldsm'd directly from it.
// x prefetch SPLIT: global load before the mma block, convert+store after.
// (UNCHANGED from the 92.4us best.)
// ---------------------------------------------------------------------------
#define TKC 32
#define NCHUNK (D_ / TKC)           // 16
#define XROW 80                     // W tile row pad (80B)
#define FROW 1040                   // full x tile row stride (512*2 + 16)
#define OFF_W  0                            // [2 stages]
#define WSTAGE (256 * XROW)                 // 20480 per stage
#define OFF_FULL (2 * WSTAGE)               // 40960, 128*1040 = 133120
#define OFF_RED (OFF_FULL + 128 * FROW)     // 174080 float[128]
#define OFF_E   (OFF_RED + 512)             // float[128]
#define OFF_IDX (OFF_E + 512)               // int[128]
#define OFF_PART (OFF_IDX + 512)            // float[4]
#define OFF_FLAG (OFF_PART + 16)            // int[1]
#define SMEM_BYTES (OFF_FLAG + 16)          // 175136
// sm_wsum[16][512] floats (32KB) reuses bytes [0, 40960) after mainloop

__global__ __launch_bounds__(1024, 1) void logits_mma_kernel(
    const float* __restrict__ x, const float* __restrict__ bias,
    const float* __restrict__ u, float* __restrict__ out)
{
    extern __shared__ char smem[];
    const uint32_t sb = smem_u32(smem);
    float* sm_red  = (float*)(smem + OFF_RED);
    float* sm_e    = (float*)(smem + OFF_E);
    int*   sm_idx  = (int*)(smem + OFF_IDX);
    float* sm_part = (float*)(smem + OFF_PART);
    int*   sm_flag = (int*)(smem + OFF_FLAG);
    float* sm_wsum = (float*)(smem);

    const int b    = blockIdx.x;
    const int jb   = blockIdx.y * 128;
    const int cnt  = g_cnt[b];
    if (jb >= cnt) return;
    const int nact = (cnt + 127) >> 7;

    const int tid  = threadIdx.x;
    const int wid  = tid >> 5;
    const int lane = tid & 31;
    const int warp_m = wid & 3;          // 32-row group
    const int warp_n = wid >> 2;         // 32-col group (0..7)

    if (tid < 128) {
        sm_red[tid] = 0.f;
        int j = jb + tid;
        sm_idx[tid] = g_idx[b * S_ + (j < cnt ? j : cnt - 1)];
    }
    __syncthreads();

    // x load mapping: 8 threads per row, float4 (4 floats) each
    const int row_x = tid >> 3;
    const int kq_x  = (tid & 7) * 4;
    const float* gx = x + ((size_t)b * S_ + sm_idx[row_x]) * D_ + kq_x;
    char* full_out = smem + OFF_FULL + row_x * FROW + kq_x * 2;

    // W cp.async mapping: 4 threads per row (n), 16B each
    const int n_w  = tid >> 2;
    const int q_w  = tid & 3;
    const __half* gw = g_WT + n_w * D_ + q_w * 8;
    const uint32_t wdst_row = n_w * XROW + q_w * 16;

    float acc[2][4][4];
#pragma unroll
    for (int i = 0; i < 2; i++)
#pragma unroll
        for (int j = 0; j < 4; j++)
#pragma unroll
            for (int k = 0; k < 4; k++) acc[i][j][k] = 0.f;

    // ---- preload chunk 0 ----
    {
        float4 v = *(const float4*)(gx);
        uint2 hi;
        hi.x = pack_h2(v.x, v.y); hi.y = pack_h2(v.z, v.w);
        *(uint2*)(full_out) = hi;

        cp16(sb + OFF_W + wdst_row, gw);
        cp_commit();
    }

    // ldmatrix lane addressing
    const int a_row  = (lane & 15);
    const int a_kb   = (lane >> 4) * 16;
    const int t      = lane >> 3;
    const int b_noff = (lane & 7) + 8 * (t >> 1);
    const int b_kb   = 16 * (t & 1);
    const uint32_t xfull = sb + OFF_FULL;

    for (int c = 0; c < NCHUNK; c++) {
        const int st  = c & 1;
        const int stn = (c + 1) & 1;

        cp_wait0();
        __syncthreads();   // chunk-c x writes + W stage visible

        // kick off chunk c+1: W cp.async + x GLOBAL LOAD ONLY (store deferred
        // past the mma block so the LDG latency hides under tensor work)
        float4 xv;
        if (c + 1 < NCHUNK) {
            cp16(sb + OFF_W + stn * WSTAGE + wdst_row, gw + (c + 1) * TKC);
            cp_commit();
            xv = *(const float4*)(gx + (c + 1) * TKC);
        }

        const uint32_t wh = sb + OFF_W + st * WSTAGE;

#pragma unroll
        for (int ks = 0; ks < 2; ks++) {
            uint32_t ah[2][4];
#pragma unroll
            for (int mt = 0; mt < 2; mt++) {
                uint32_t ra = (warp_m * 32 + mt * 16 + a_row) * FROW
                            + c * 64 + ks * 32 + a_kb;
                ldsm_x4(xfull + ra, ah[mt][0], ah[mt][1], ah[mt][2], ah[mt][3]);
            }
#pragma unroll
            for (int pair = 0; pair < 2; pair++) {
                uint32_t rb = (warp_n * 32 + pair * 16 + b_noff) * XROW + ks * 32 + b_kb;
                uint32_t bh0, bh1, bh2, bh3;
                ldsm_x4(wh + rb, bh0, bh1, bh2, bh3);
#pragma unroll
                for (int mt = 0; mt < 2; mt++) {
                    mma_f16(acc[mt][pair * 2 + 0], ah[mt], bh0, bh1);
                    mma_f16(acc[mt][pair * 2 + 1], ah[mt], bh2, bh3);
                }
            }
        }

        // deferred convert + store of chunk c+1 (disjoint region; ordered by
        // the next iteration's barrier before any reader touches it)
        if (c + 1 < NCHUNK) {
            uint2 hi;
            hi.x = pack_h2(xv.x, xv.y); hi.y = pack_h2(xv.z, xv.w);
            *(uint2*)(full_out + (c + 1) * (TKC * 2)) = hi;
        }
    }

    // ---- epilogue 1: tanh(acc + bias) * u, reduce over cols ----
#pragma unroll
    for (int mt = 0; mt < 2; mt++) {
        float r0acc = 0.f, r1acc = 0.f;
#pragma unroll
        for (int j = 0; j < 4; j++) {
            int col = warp_n * 32 + j * 8 + 2 * (lane & 3);
            float b0 = bias[col], b1 = bias[col + 1];
            float u0 = u[col],    u1 = u[col + 1];
            r0acc += tanh_fast(acc[mt][j][0] + b0) * u0
                   + tanh_fast(acc[mt][j][1] + b1) * u1;
            r1acc += tanh_fast(acc[mt][j][2] + b0) * u0
                   + tanh_fast(acc[mt][j][3] + b1) * u1;
        }
        r0acc += __shfl_xor_sync(0xffffffffu, r0acc, 1);
        r0acc += __shfl_xor_sync(0xffffffffu, r0acc, 2);
        r1acc += __shfl_xor_sync(0xffffffffu, r1acc, 1);
        r1acc += __shfl_xor_sync(0xffffffffu, r1acc, 2);
        if ((lane & 3) == 0) {
            int lrow = warp_m * 32 + mt * 16 + (lane >> 2);
            atomicAdd(&sm_red[lrow],     r0acc);
            atomicAdd(&sm_red[lrow + 8], r1acc);
        }
    }
    __syncthreads();

    // ---- epilogue 2: e = exp(logit) (0 past cnt), esum partial ----
    if (tid < 128) {
        int j = jb + tid;
        float e = (j < cnt) ? expf(sm_red[tid]) : 0.f;
        sm_e[tid] = e;
        float v = e;
#pragma unroll
        for (int off = 16; off > 0; off >>= 1)
            v += __shfl_xor_sync(0xffffffffu, v, off);
        if (lane == 0) sm_part[wid] = v;
    }
    __syncthreads();
    if (tid == 0)
        atomicAdd(&g_esum[b], sm_part[0] + sm_part[1] + sm_part[2] + sm_part[3]);

    // ---- epilogue 3: fused weighted sum from SMEM-resident x tile ----
    {
        const int g  = tid >> 6;               // 0..15
        const int d8 = (tid & 63) * 8;
        float a8[8];
#pragma unroll
        for (int i = 0; i < 8; i++) a8[i] = 0.f;

        const char* xb = smem + OFF_FULL + d8 * 2;
#pragma unroll 4
        for (int j = g; j < 128; j += 16) {
            uint4 v = *(const uint4*)(xb + j * FROW);
            float w = sm_e[j];
            float2 f0 = __half22float2(*(__half2*)&v.x);
            float2 f1 = __half22float2(*(__half2*)&v.y);
            float2 f2 = __half22float2(*(__half2*)&v.z);
            float2 f3 = __half22float2(*(__half2*)&v.w);
            a8[0] = fmaf(f0.x, w, a8[0]); a8[1] = fmaf(f0.y, w, a8[1]);
            a8[2] = fmaf(f1.x, w, a8[2]); a8[3] = fmaf(f1.y, w, a8[3]);
            a8[4] = fmaf(f2.x, w, a8[4]); a8[5] = fmaf(f2.y, w, a8[5]);
            a8[6] = fmaf(f3.x, w, a8[6]); a8[7] = fmaf(f3.y, w, a8[7]);
        }
        __syncthreads();   // W-stage smem now reusable as sm_wsum
        *(float4*)(&sm_wsum[g * 512 + d8])     = make_float4(a8[0], a8[1], a8[2], a8[3]);
        *(float4*)(&sm_wsum[g * 512 + d8 + 4]) = make_float4(a8[4], a8[5], a8[6], a8[7]);
    }
    __syncthreads();
    if (tid < 512) {
        float s = 0.f;
#pragma unroll
        for (int g = 0; g < 16; g++) s += sm_wsum[g * 512 + tid];
        atomicAdd(&g_outacc[b * 512 + tid], s);
    }
    __syncthreads();

    // ---- epilogue 4: last CTA for this batch writes the scaled output ----
    if (tid == 0) {
        __threadfence();
        int ticket = atomicAdd(&g_done[b], 1);
        sm_flag[0] = (ticket == nact - 1);
    }
    __syncthreads();
    if (sm_flag[0] && tid < 512) {
        __threadfence();
        const float inv = __fdividef(1.f, g_esum[b] + 1e-7f);
        out[b * 512 + tid] = g_outacc[b * 512 + tid] * inv;
    }
}

// ---------------------------------------------------------------------------
extern "C" void kernel_launch(void* const* d_in, const int* in_sizes, int n_in,
                              void* d_out, int out_size)
{
    const float* x    = (const float*)d_in[0];
    const int*   mask = (const int*)d_in[1];
    const float* W    = (const float*)d_in[2];
    const float* bias = (const float*)d_in[3];
    const float* u    = (const float*)d_in[4];
    float*       out  = (float*)d_out;

    cudaFuncSetAttribute(logits_mma_kernel,
                         cudaFuncAttributeMaxDynamicSharedMemorySize, SMEM_BYTES);

    compact_kernel<<<B_, 1024>>>(mask, W);
    logits_mma_kernel<<<dim3(B_, 16), 1024, SMEM_BYTES>>>(x, bias, u, out);
}